// round 1
// baseline (speedup 1.0000x reference)
#include <cuda_runtime.h>
#include <math.h>

// Problem constants
#define BN 8
#define CC 256
#define CI 512        // 2C
#define HH 64
#define WW 64
#define KK 4
#define HW (HH*WW)          // 4096
#define CHW (CC*HW)         // 1048576
#define NOUT (BN*CHW)       // 8388608 per tensor

// ---------------- scratch (device globals; no allocation allowed) ----------
__device__ float g_Fm[NOUT];                 // conv+leaky output  (33.5 MB)
__device__ float g_U1[BN*CC*KK];
__device__ float g_U2[BN*WW*KK];
__device__ float g_U3[BN*HH*KK];
__device__ float g_Mc[3*KK*3];               // per mode m,k: {m_avg, m_max, c}
__device__ float g_spatial[BN*HW];
__device__ float g_spec[BN*CC];
__device__ float g_ga[BN*CC];
__device__ float g_gm[BN*CC];
__device__ float g_V1[BN*CC*KK];

// ---------------- K0: fold adapters into 2->K affine -----------------------
__global__ void precompute_kernel(const float* __restrict__ Wu, const float* __restrict__ bu,
                                  const float* __restrict__ Wa1, const float* __restrict__ ba1,
                                  const float* __restrict__ Wa2, const float* __restrict__ ba2,
                                  const float* __restrict__ Wa3, const float* __restrict__ ba3) {
    int t = threadIdx.x;
    if (t >= 12) return;
    int m = t >> 2, k = t & 3;
    const float* Wa = (m == 0) ? Wa1 : ((m == 1) ? Wa2 : Wa3);
    const float* ba = (m == 0) ? ba1 : ((m == 1) ? ba2 : ba3);
    float m0 = 0.f, m1 = 0.f, cc = 0.f;
    for (int o = 0; o < CC; o++) {
        float wu = Wu[k * CC + o];
        m0 += wu * Wa[o * 2 + 0];
        m1 += wu * Wa[o * 2 + 1];
        cc += wu * ba[o];
    }
    g_Mc[(m * KK + k) * 3 + 0] = m0;
    g_Mc[(m * KK + k) * 3 + 1] = m1;
    g_Mc[(m * KK + k) * 3 + 2] = cc + bu[k];
}

// ---------------- K1: conv3x3 (2C->C, SAME) + leaky_relu -------------------
// block: 256 thr (16x16). tile: 8 co x 32x32 spatial, 2x2 micro-tile/thread.
__global__ __launch_bounds__(256) void conv3x3_kernel(
    const float* __restrict__ frm, const float* __restrict__ other,
    const float* __restrict__ W3, const float* __restrict__ b3) {
    const int tid = threadIdx.x;
    const int tx = tid & 15;
    const int ty = tid >> 4;
    const int x0 = (blockIdx.x & 1) * 32;
    const int y0 = (blockIdx.x >> 1) * 32;
    const int co0 = blockIdx.y * 8;
    const int b = blockIdx.z;

    __shared__ float sIn[34][36];
    __shared__ float sW[8][9];

    float acc[8][4];
#pragma unroll
    for (int i = 0; i < 8; i++)
#pragma unroll
        for (int j = 0; j < 4; j++) acc[i][j] = 0.f;

    for (int ci = 0; ci < CI; ci++) {
        const float* src = (ci < CC) ? (frm + ((size_t)(b * CC + ci)) * HW)
                                     : (other + ((size_t)(b * CC + (ci - CC))) * HW);
        __syncthreads();
        // load 34x34 halo tile (rows y0-1..y0+32, cols x0-1..x0+32), zero-pad
        for (int i = tid; i < 34 * 34; i += 256) {
            int r = i / 34, c2 = i - r * 34;
            int gy = y0 - 1 + r, gx = x0 - 1 + c2;
            float v = 0.f;
            if (gy >= 0 && gy < HH && gx >= 0 && gx < WW) v = src[gy * WW + gx];
            sIn[r][c2] = v;
        }
        if (tid < 72) {
            int co = tid / 9, t9 = tid - co * 9;
            sW[co][t9] = W3[((size_t)(co0 + co) * CI + ci) * 9 + t9];
        }
        __syncthreads();

        float in[4][4];
#pragma unroll
        for (int i = 0; i < 4; i++)
#pragma unroll
            for (int j = 0; j < 4; j++) in[i][j] = sIn[2 * ty + i][2 * tx + j];

#pragma unroll
        for (int co = 0; co < 8; co++) {
#pragma unroll
            for (int ky = 0; ky < 3; ky++)
#pragma unroll
                for (int kx = 0; kx < 3; kx++) {
                    float w = sW[co][ky * 3 + kx];
                    acc[co][0] = fmaf(w, in[ky    ][kx    ], acc[co][0]);
                    acc[co][1] = fmaf(w, in[ky    ][kx + 1], acc[co][1]);
                    acc[co][2] = fmaf(w, in[ky + 1][kx    ], acc[co][2]);
                    acc[co][3] = fmaf(w, in[ky + 1][kx + 1], acc[co][3]);
                }
        }
    }

#pragma unroll
    for (int co = 0; co < 8; co++) {
        float bb = b3[co0 + co];
#pragma unroll
        for (int dy = 0; dy < 2; dy++)
#pragma unroll
            for (int dx = 0; dx < 2; dx++) {
                float v = acc[co][dy * 2 + dx] + bb;
                v = (v > 0.f) ? v : 0.01f * v;
                int y = y0 + 2 * ty + dy, x = x0 + 2 * tx + dx;
                g_Fm[((size_t)(b * CC + co0 + co) * HH + y) * WW + x] = v;
            }
    }
}

// ---------------- K2: mode poolings + U softmax -----------------------------
// blocks: 0..2047 mode1 (b,c over HW); 2048..2559 mode2 (b,w over C*H);
//         2560..3071 mode3 (b,h over C*W)
__global__ __launch_bounds__(256) void modes_kernel() {
    __shared__ float sSum[256];
    __shared__ float sMax[256];
    const int bid = blockIdx.x, tid = threadIdx.x;
    int mode, b, n;
    float cnt;
    float s = 0.f, mx = -3.4e38f;

    if (bid < 2048) {
        mode = 0; b = bid >> 8; n = bid & 255; cnt = (float)HW;
        const float* p = g_Fm + ((size_t)(b * CC + n) << 12);
        for (int j = tid; j < HW; j += 256) { float v = p[j]; s += v; mx = fmaxf(mx, v); }
    } else if (bid < 2560) {
        mode = 1; int r = bid - 2048; b = r >> 6; n = r & 63; cnt = (float)(CC * HH);
        const float* p = g_Fm + (size_t)b * CHW + n;          // + c*HW + h*WW
        for (int j = tid; j < CC * HH; j += 256) {
            int c = j >> 6, h = j & 63;
            float v = p[(size_t)c * HW + h * WW];
            s += v; mx = fmaxf(mx, v);
        }
    } else {
        mode = 2; int r = bid - 2560; b = r >> 6; n = r & 63; cnt = (float)(CC * WW);
        const float* p = g_Fm + (size_t)b * CHW + (size_t)n * WW;  // + c*HW + w
        for (int j = tid; j < CC * WW; j += 256) {
            int c = j >> 6, w = j & 63;
            float v = p[(size_t)c * HW + w];
            s += v; mx = fmaxf(mx, v);
        }
    }
    sSum[tid] = s; sMax[tid] = mx;
    __syncthreads();
    for (int st = 128; st > 0; st >>= 1) {
        if (tid < st) {
            sSum[tid] += sSum[tid + st];
            sMax[tid] = fmaxf(sMax[tid], sMax[tid + st]);
        }
        __syncthreads();
    }
    if (tid == 0) {
        float avg = sSum[0] / cnt, mxv = sMax[0];
        float u[4], um = -3.4e38f;
#pragma unroll
        for (int k = 0; k < 4; k++) {
            const float* mc = &g_Mc[(mode * KK + k) * 3];
            u[k] = mc[0] * avg + mc[1] * mxv + mc[2];
            um = fmaxf(um, u[k]);
        }
        float es = 0.f;
#pragma unroll
        for (int k = 0; k < 4; k++) { u[k] = expf(u[k] - um); es += u[k]; }
        float inv = 1.f / es;
        float* U = (mode == 0) ? g_U1 : ((mode == 1) ? g_U2 : g_U3);
#pragma unroll
        for (int k = 0; k < 4; k++) U[(size_t)(b * ((mode == 0) ? CC : 64) + n) * 4 + k] = u[k] * inv;
    }
}

// ---------------- K3: spatial, ga/gm, V1 ------------------------------------
__global__ __launch_bounds__(256) void small_kernel(const float* __restrict__ Wr,
                                                    const float* __restrict__ lam,
                                                    const float* __restrict__ ws_p,
                                                    const float* __restrict__ bs_p) {
    const int bid = blockIdx.x, tid = threadIdx.x;
    if (bid < 128) {
        // spatial[b,h,w] = sigmoid(ws * dot(U3[b,h], U2[b,w]) + bs)
        int g = bid * 256 + tid;
        int b = g >> 12, p = g & 4095;
        int h = p >> 6, w = p & 63;
        const float* u3 = &g_U3[(b * 64 + h) * 4];
        const float* u2 = &g_U2[(b * 64 + w) * 4];
        float d = u3[0] * u2[0] + u3[1] * u2[1] + u3[2] * u2[2] + u3[3] * u2[3];
        float v = ws_p[0] * d + bs_p[0];
        g_spatial[g] = 1.f / (1.f + expf(-v));
    } else if (bid < 136) {
        // ga/gm per (b,c) over n=0..127 of F_spe = U1 . Ucat
        int g = (bid - 128) * 256 + tid;
        int b = g >> 8;
        const float* u1 = &g_U1[(size_t)g * 4];
        float a0 = u1[0], a1 = u1[1], a2 = u1[2], a3 = u1[3];
        float s = 0.f, m = -3.4e38f;
        for (int n = 0; n < 128; n++) {
            const float* uc = (n < 64) ? &g_U2[(b * 64 + n) * 4] : &g_U3[(b * 64 + (n - 64)) * 4];
            float d = a0 * uc[0] + a1 * uc[1] + a2 * uc[2] + a3 * uc[3];
            s += d; m = fmaxf(m, d);
        }
        g_ga[g] = s * (1.f / 128.f);
        g_gm[g] = m;
    } else {
        // V1[b,o,r] = lam[r] * sum_i Wr[o,i] * U1[b,i,r]
        int g = (bid - 136) * 256 + tid;
        int b = g >> 8, o = g & 255;
        const float* wr = &Wr[(size_t)o * CC];
        const float* u1 = &g_U1[(size_t)b * CC * 4];
        float s0 = 0.f, s1 = 0.f, s2 = 0.f, s3 = 0.f;
        for (int i = 0; i < CC; i++) {
            float w = wr[i];
            const float* u = &u1[i * 4];
            s0 = fmaf(w, u[0], s0); s1 = fmaf(w, u[1], s1);
            s2 = fmaf(w, u[2], s2); s3 = fmaf(w, u[3], s3);
        }
        float* v = &g_V1[(size_t)g * 4];
        v[0] = lam[0] * s0; v[1] = lam[1] * s1; v[2] = lam[2] * s2; v[3] = lam[3] * s3;
    }
}

// ---------------- K4: spectral ----------------------------------------------
__global__ __launch_bounds__(256) void spectral_kernel(const float* __restrict__ Wsa,
                                                       const float* __restrict__ bsa,
                                                       const float* __restrict__ Wsm,
                                                       const float* __restrict__ bsm) {
    int g = blockIdx.x * 256 + threadIdx.x;   // 0..2047
    int b = g >> 8, o = g & 255;
    const float* ga = &g_ga[b * CC];
    const float* gm = &g_gm[b * CC];
    const float* wa = &Wsa[(size_t)o * CC];
    const float* wm = &Wsm[(size_t)o * CC];
    float s = bsa[o] + bsm[o];
    for (int i = 0; i < CC; i++) s += wa[i] * ga[i] + wm[i] * gm[i];
    float t = 1.f / (1.f + expf(-s));
    g_spec[g] = 1.f / (1.f + expf(-t));
}

// ---------------- K5: fused epilogue (both outputs) -------------------------
// NOTE einsum "bcr,bhr,bwr": U2 is indexed by h, U3 by w.
__global__ __launch_bounds__(256) void epilogue_kernel(const float* __restrict__ frm,
                                                       const float* __restrict__ other,
                                                       const float* __restrict__ br,
                                                       const float* __restrict__ alpha_p,
                                                       float* __restrict__ out) {
    int e = blockIdx.x * 256 + threadIdx.x;   // each handles 4 consecutive w
    int i4 = e * 4;
    int b = i4 >> 20;
    int c = (i4 >> 12) & 255;
    int h = (i4 >> 6) & 63;
    int w0 = i4 & 63;

    float alpha = alpha_p[0];
    float spec = g_spec[b * CC + c];
    const float* sp = &g_spatial[(b * HH + h) * WW + w0];
    float4 f4 = *(const float4*)&frm[i4];
    float4 o4 = *(const float4*)&other[i4];
    float4 m4 = *(const float4*)&g_Fm[i4];

    const float* v1 = &g_V1[(size_t)(b * CC + c) * 4];
    const float* u2h = &g_U2[(b * 64 + h) * 4];       // h-indexed factor is U2
    float vr0 = v1[0] * u2h[0], vr1 = v1[1] * u2h[1];
    float vr2 = v1[2] * u2h[2], vr3 = v1[3] * u2h[3];
    float brc = br[c];

    float fu[4], cr[4];
    float fr[4] = {f4.x, f4.y, f4.z, f4.w};
    float ot[4] = {o4.x, o4.y, o4.z, o4.w};
    float fm[4] = {m4.x, m4.y, m4.z, m4.w};
#pragma unroll
    for (int j = 0; j < 4; j++) {
        float wt = spec * sp[j];
        fu[j] = alpha * wt * fr[j] + (1.f - alpha) * (1.f - wt) * ot[j];
        const float* u3w = &g_U3[(b * 64 + w0 + j) * 4];   // w-indexed factor is U3
        float cp = brc + vr0 * u3w[0] + vr1 * u3w[1] + vr2 * u3w[2] + vr3 * u3w[3];
        cr[j] = cp * wt + fm[j];
    }
    *(float4*)&out[i4] = make_float4(fu[0], fu[1], fu[2], fu[3]);
    *(float4*)&out[NOUT + i4] = make_float4(cr[0], cr[1], cr[2], cr[3]);
}

// ---------------- launch -----------------------------------------------------
extern "C" void kernel_launch(void* const* d_in, const int* in_sizes, int n_in,
                              void* d_out, int out_size) {
    const float* frm   = (const float*)d_in[0];
    const float* other = (const float*)d_in[1];
    const float* W3    = (const float*)d_in[2];
    const float* b3    = (const float*)d_in[3];
    const float* Wa1   = (const float*)d_in[4];
    const float* ba1   = (const float*)d_in[5];
    const float* Wa2   = (const float*)d_in[6];
    const float* ba2   = (const float*)d_in[7];
    const float* Wa3   = (const float*)d_in[8];
    const float* ba3   = (const float*)d_in[9];
    const float* Wu    = (const float*)d_in[10];
    const float* bu    = (const float*)d_in[11];
    const float* Wr    = (const float*)d_in[12];
    const float* br    = (const float*)d_in[13];
    const float* ws    = (const float*)d_in[14];
    const float* bs    = (const float*)d_in[15];
    const float* Wsa   = (const float*)d_in[16];
    const float* bsa   = (const float*)d_in[17];
    const float* Wsm   = (const float*)d_in[18];
    const float* bsm   = (const float*)d_in[19];
    const float* alpha = (const float*)d_in[20];
    const float* lam   = (const float*)d_in[21];
    float* out = (float*)d_out;

    precompute_kernel<<<1, 32>>>(Wu, bu, Wa1, ba1, Wa2, ba2, Wa3, ba3);
    conv3x3_kernel<<<dim3(4, 32, 8), 256>>>(frm, other, W3, b3);
    modes_kernel<<<3072, 256>>>();
    small_kernel<<<144, 256>>>(Wr, lam, ws, bs);
    spectral_kernel<<<8, 256>>>(Wsa, bsa, Wsm, bsm);
    epilogue_kernel<<<NOUT / 4 / 256, 256>>>(frm, other, br, alpha, out);
}

// round 3
// speedup vs baseline: 5.1113x; 5.1113x over previous
#include <cuda_runtime.h>
#include <cuda_bf16.h>
#include <math.h>
#include <stdint.h>

// Problem constants
#define BN 8
#define CC 256
#define CI 512        // 2C
#define HH 64
#define WW 64
#define KK 4
#define HW (HH*WW)          // 4096
#define CHW (CC*HW)         // 1048576
#define NOUT (BN*CHW)       // 8388608 per tensor
#define KTOT 4608           // CI*9

// ---------------- scratch (device globals; no allocation allowed) ----------
__device__ float g_Fm[NOUT];                        // conv+leaky output (fp32 NCHW)
__device__ __nv_bfloat16 g_Xhi[BN*HH*WW*CI];        // NHWC bf16 hi
__device__ __nv_bfloat16 g_Xlo[BN*HH*WW*CI];        // NHWC bf16 lo
__device__ __nv_bfloat16 g_Whi[CC*KTOT];            // [co][tap*512+ci] hi
__device__ __nv_bfloat16 g_Wlo[CC*KTOT];            // lo
__device__ float g_U1[BN*CC*KK];
__device__ float g_U2[BN*WW*KK];
__device__ float g_U3[BN*HH*KK];
__device__ float g_Mc[3*KK*3];
__device__ float g_spatial[BN*HW];
__device__ float g_spec[BN*CC];
__device__ float g_ga[BN*CC];
__device__ float g_gm[BN*CC];
__device__ float g_V1[BN*CC*KK];

// ================= PTX helpers ==============================================
__device__ __forceinline__ uint32_t smem_u32(const void* p) {
    uint32_t a;
    asm("{ .reg .u64 t; cvta.to.shared.u64 t, %1; cvt.u32.u64 %0, t; }" : "=r"(a) : "l"(p));
    return a;
}
__device__ __forceinline__ void cp_async16(uint32_t dst, const void* src, uint32_t srcSize) {
    asm volatile("cp.async.ca.shared.global [%0], [%1], 16, %2;"
                 :: "r"(dst), "l"(src), "r"(srcSize) : "memory");
}
#define CP_COMMIT() asm volatile("cp.async.commit_group;" ::: "memory")
#define CP_WAIT(n)  asm volatile("cp.async.wait_group %0;" :: "n"(n) : "memory")

__device__ __forceinline__ void ldsm4(uint32_t addr, uint32_t r[4]) {
    asm volatile("ldmatrix.sync.aligned.m8n8.x4.shared.b16 {%0,%1,%2,%3}, [%4];"
                 : "=r"(r[0]), "=r"(r[1]), "=r"(r[2]), "=r"(r[3]) : "r"(addr));
}
__device__ __forceinline__ void mma16816(float c[4], const uint32_t a[4], const uint32_t b[2]) {
    asm volatile("mma.sync.aligned.m16n8k16.row.col.f32.bf16.bf16.f32 "
                 "{%0,%1,%2,%3}, {%4,%5,%6,%7}, {%8,%9}, {%0,%1,%2,%3};"
                 : "+f"(c[0]), "+f"(c[1]), "+f"(c[2]), "+f"(c[3])
                 : "r"(a[0]), "r"(a[1]), "r"(a[2]), "r"(a[3]), "r"(b[0]), "r"(b[1]));
}
#define SWZ(x) ((x) ^ (((x) >> 3) & 0x70))

// ---------------- K0: fold adapters into 2->K affine -----------------------
__global__ void precompute_kernel(const float* __restrict__ Wu, const float* __restrict__ bu,
                                  const float* __restrict__ Wa1, const float* __restrict__ ba1,
                                  const float* __restrict__ Wa2, const float* __restrict__ ba2,
                                  const float* __restrict__ Wa3, const float* __restrict__ ba3) {
    int t = threadIdx.x;
    if (t >= 12) return;
    int m = t >> 2, k = t & 3;
    const float* Wa = (m == 0) ? Wa1 : ((m == 1) ? Wa2 : Wa3);
    const float* ba = (m == 0) ? ba1 : ((m == 1) ? ba2 : ba3);
    float m0 = 0.f, m1 = 0.f, cc = 0.f;
    for (int o = 0; o < CC; o++) {
        float wu = Wu[k * CC + o];
        m0 += wu * Wa[o * 2 + 0];
        m1 += wu * Wa[o * 2 + 1];
        cc += wu * ba[o];
    }
    g_Mc[(m * KK + k) * 3 + 0] = m0;
    g_Mc[(m * KK + k) * 3 + 1] = m1;
    g_Mc[(m * KK + k) * 3 + 2] = cc + bu[k];
}

// ---------------- prep: weights -> [co][tap*512+ci] bf16 hi/lo --------------
__global__ __launch_bounds__(256) void prep_w_kernel(const float* __restrict__ W3) {
    int co = blockIdx.y;
    int r = blockIdx.x * 256 + threadIdx.x;   // 0..4607
    int tap = r >> 9, ci = r & 511;
    float v = W3[((size_t)co * CI + ci) * 9 + tap];
    __nv_bfloat16 h = __float2bfloat16_rn(v);
    __nv_bfloat16 l = __float2bfloat16_rn(v - __bfloat162float(h));
    g_Whi[(size_t)co * KTOT + r] = h;
    g_Wlo[(size_t)co * KTOT + r] = l;
}

// ---------------- prep: inputs NCHW fp32 -> NHWC bf16 hi/lo -----------------
__global__ __launch_bounds__(256) void prep_x_kernel(const float* __restrict__ frm,
                                                     const float* __restrict__ other) {
    __shared__ float S[64][65];
    int by = blockIdx.x;           // b*64 + y
    int b = by >> 6, y = by & 63;
    int cc = blockIdx.y;           // ci chunk of 64
    int tid = threadIdx.x;
#pragma unroll
    for (int i = 0; i < 16; i++) {
        int idx = i * 256 + tid;
        int ciL = idx >> 6, x = idx & 63;
        int ciX = cc * 64 + ciL;
        const float* src = (ciX < CC) ? frm : other;
        int cs = ciX & 255;
        S[ciL][x] = src[((size_t)(b * CC + cs) * HH + y) * WW + x];
    }
    __syncthreads();
#pragma unroll
    for (int i = 0; i < 16; i++) {
        int idx = i * 256 + tid;
        int x = idx >> 6, ciL = idx & 63;
        float v = S[ciL][x];
        __nv_bfloat16 h = __float2bfloat16_rn(v);
        __nv_bfloat16 l = __float2bfloat16_rn(v - __bfloat162float(h));
        size_t d = ((size_t)(b * 64 + y) * 64 + x) * CI + cc * 64 + ciL;
        g_Xhi[d] = h;
        g_Xlo[d] = l;
    }
}

// ---------------- conv via mma.sync bf16x3 implicit GEMM --------------------
// CTA: M=128 pixels (2 rows), N=128 co. 8 warps = 4M x 2N, warp tile 32x64.
// K = 72 chunks of 64 (9 taps x 8 ci-chunks). Stage: Ahi|Alo|Bhi|Blo 16KB each.
#define STAGE_BYTES 65536
#define DSMEM_BYTES (2*STAGE_BYTES + 1024)

__device__ __forceinline__ void stage_load(uint32_t smStage, int b, int y0, int n0,
                                           int c, int tid) {
    const int tap = c >> 3, cic = c & 7;
    const int ky = tap / 3 - 1, kx = tap % 3 - 1;
#pragma unroll
    for (int i = 0; i < 8; i++) {
        int idx = i * 256 + tid;
        int plane = idx >> 10, rem = idx & 1023;
        int r = rem >> 3, q = rem & 7;
        int ys = y0 + (r >> 6) + ky, xs = (r & 63) + kx;
        bool ok = ((unsigned)ys < 64u) && ((unsigned)xs < 64u);
        const __nv_bfloat16* base = plane ? g_Xlo : g_Xhi;
        const void* src = ok
            ? (const void*)(base + (((size_t)(b * 64 + ys) * 64 + xs) * CI + cic * 64 + q * 8))
            : (const void*)base;
        uint32_t full = (uint32_t)(r * 128 + q * 16);
        cp_async16(smStage + plane * 16384 + SWZ(full), src, ok ? 16u : 0u);
    }
#pragma unroll
    for (int i = 0; i < 8; i++) {
        int idx = i * 256 + tid;
        int plane = idx >> 10, rem = idx & 1023;
        int r = rem >> 3, q = rem & 7;
        const __nv_bfloat16* base = plane ? g_Wlo : g_Whi;
        const void* src = base + ((size_t)(n0 * 128 + r) * KTOT + c * 64 + q * 8);
        uint32_t full = (uint32_t)(r * 128 + q * 16);
        cp_async16(smStage + 32768 + plane * 16384 + SWZ(full), src, 16u);
    }
}

__global__ __launch_bounds__(256, 1)
void conv_mma_kernel(const float* __restrict__ b3) {
    extern __shared__ __align__(128) char dynsm_raw[];
    const uint32_t smBase = (smem_u32(dynsm_raw) + 1023) & ~1023u;

    const int tid = threadIdx.x;
    const int lane = tid & 31;
    const int w = tid >> 5;
    const int wm = w & 3, wn = w >> 2;
    const int mIdx = blockIdx.x;
    const int b = mIdx >> 5;
    const int y0 = (mIdx & 31) * 2;
    const int n0 = blockIdx.y;

    float acc[2][8][4];
#pragma unroll
    for (int mf = 0; mf < 2; mf++)
#pragma unroll
        for (int nf = 0; nf < 8; nf++)
#pragma unroll
            for (int j = 0; j < 4; j++) acc[mf][nf][j] = 0.f;

    // fragment address components (bytes within region)
    const uint32_t aRowOff = (uint32_t)((wm * 32 + (lane & 15)) * 128);
    const uint32_t aColB   = (uint32_t)((lane >> 4) * 16);
    const uint32_t bRowOff = (uint32_t)((wn * 64 + (lane & 7) + ((lane >> 4) << 3)) * 128);
    const uint32_t bColB   = (uint32_t)(((lane >> 3) & 1) * 16);

    stage_load(smBase, b, y0, n0, 0, tid);
    CP_COMMIT();
    stage_load(smBase + STAGE_BYTES, b, y0, n0, 1, tid);
    CP_COMMIT();

    for (int c = 0; c < 72; c++) {
        if (c < 71) { CP_WAIT(1); } else { CP_WAIT(0); }
        __syncthreads();

        const uint32_t st = smBase + (uint32_t)(c & 1) * STAGE_BYTES;
#pragma unroll
        for (int k16 = 0; k16 < 4; k16++) {
            const uint32_t kb = (uint32_t)(k16 * 32);
            uint32_t ah[2][4], al[2][4], bh[8][2], bl[8][2];
            // A hi
#pragma unroll
            for (int mf = 0; mf < 2; mf++) {
                uint32_t full = aRowOff + (uint32_t)(mf * 2048) + aColB + kb;
                ldsm4(st + SWZ(full), ah[mf]);
            }
            // B hi
#pragma unroll
            for (int jp = 0; jp < 4; jp++) {
                uint32_t full = bRowOff + (uint32_t)(jp * 2048) + bColB + kb;
                uint32_t r[4];
                ldsm4(st + 32768 + SWZ(full), r);
                bh[2 * jp][0] = r[0]; bh[2 * jp][1] = r[1];
                bh[2 * jp + 1][0] = r[2]; bh[2 * jp + 1][1] = r[3];
            }
            // hi x hi
#pragma unroll
            for (int mf = 0; mf < 2; mf++)
#pragma unroll
                for (int nf = 0; nf < 8; nf++) mma16816(acc[mf][nf], ah[mf], bh[nf]);
            // B lo
#pragma unroll
            for (int jp = 0; jp < 4; jp++) {
                uint32_t full = bRowOff + (uint32_t)(jp * 2048) + bColB + kb;
                uint32_t r[4];
                ldsm4(st + 49152 + SWZ(full), r);
                bl[2 * jp][0] = r[0]; bl[2 * jp][1] = r[1];
                bl[2 * jp + 1][0] = r[2]; bl[2 * jp + 1][1] = r[3];
            }
            // hi x lo
#pragma unroll
            for (int mf = 0; mf < 2; mf++)
#pragma unroll
                for (int nf = 0; nf < 8; nf++) mma16816(acc[mf][nf], ah[mf], bl[nf]);
            // A lo
#pragma unroll
            for (int mf = 0; mf < 2; mf++) {
                uint32_t full = aRowOff + (uint32_t)(mf * 2048) + aColB + kb;
                ldsm4(st + 16384 + SWZ(full), al[mf]);
            }
            // lo x hi
#pragma unroll
            for (int mf = 0; mf < 2; mf++)
#pragma unroll
                for (int nf = 0; nf < 8; nf++) mma16816(acc[mf][nf], al[mf], bh[nf]);
        }
        __syncthreads();
        if (c + 2 < 72) {
            stage_load(smBase + (uint32_t)(c & 1) * STAGE_BYTES, b, y0, n0, c + 2, tid);
            CP_COMMIT();
        }
    }

    // epilogue: bias + leaky relu -> g_Fm (NCHW)
    const int rr = wm * 32 + (lane >> 2);
    const int cc0 = n0 * 128 + wn * 64 + (lane & 3) * 2;
    const int pixBase = y0 * 64;
#pragma unroll
    for (int mf = 0; mf < 2; mf++) {
        int r0 = rr + mf * 16;
#pragma unroll
        for (int nf = 0; nf < 8; nf++) {
            int co = cc0 + nf * 8;
            float bi0 = __ldg(&b3[co]), bi1 = __ldg(&b3[co + 1]);
            float v0 = acc[mf][nf][0] + bi0;
            float v1 = acc[mf][nf][1] + bi1;
            float v2 = acc[mf][nf][2] + bi0;
            float v3 = acc[mf][nf][3] + bi1;
            v0 = (v0 > 0.f) ? v0 : 0.01f * v0;
            v1 = (v1 > 0.f) ? v1 : 0.01f * v1;
            v2 = (v2 > 0.f) ? v2 : 0.01f * v2;
            v3 = (v3 > 0.f) ? v3 : 0.01f * v3;
            size_t base0 = ((size_t)(b * CC + co) << 12) + pixBase;
            size_t base1 = ((size_t)(b * CC + co + 1) << 12) + pixBase;
            g_Fm[base0 + r0] = v0;
            g_Fm[base1 + r0] = v1;
            g_Fm[base0 + r0 + 8] = v2;
            g_Fm[base1 + r0 + 8] = v3;
        }
    }
}

// ---------------- K2: mode poolings + U softmax -----------------------------
__global__ __launch_bounds__(256) void modes_kernel() {
    __shared__ float sSum[256];
    __shared__ float sMax[256];
    const int bid = blockIdx.x, tid = threadIdx.x;
    int mode, b, n;
    float cnt;
    float s = 0.f, mx = -3.4e38f;

    if (bid < 2048) {
        mode = 0; b = bid >> 8; n = bid & 255; cnt = (float)HW;
        const float* p = g_Fm + ((size_t)(b * CC + n) << 12);
        for (int j = tid; j < HW; j += 256) { float v = p[j]; s += v; mx = fmaxf(mx, v); }
    } else if (bid < 2560) {
        mode = 1; int r = bid - 2048; b = r >> 6; n = r & 63; cnt = (float)(CC * HH);
        const float* p = g_Fm + (size_t)b * CHW + n;
        for (int j = tid; j < CC * HH; j += 256) {
            int c = j >> 6, h = j & 63;
            float v = p[(size_t)c * HW + h * WW];
            s += v; mx = fmaxf(mx, v);
        }
    } else {
        mode = 2; int r = bid - 2560; b = r >> 6; n = r & 63; cnt = (float)(CC * WW);
        const float* p = g_Fm + (size_t)b * CHW + (size_t)n * WW;
        for (int j = tid; j < CC * WW; j += 256) {
            int c = j >> 6, w = j & 63;
            float v = p[(size_t)c * HW + w];
            s += v; mx = fmaxf(mx, v);
        }
    }
    sSum[tid] = s; sMax[tid] = mx;
    __syncthreads();
    for (int st = 128; st > 0; st >>= 1) {
        if (tid < st) {
            sSum[tid] += sSum[tid + st];
            sMax[tid] = fmaxf(sMax[tid], sMax[tid + st]);
        }
        __syncthreads();
    }
    if (tid == 0) {
        float avg = sSum[0] / cnt, mxv = sMax[0];
        float u[4], um = -3.4e38f;
#pragma unroll
        for (int k = 0; k < 4; k++) {
            const float* mc = &g_Mc[(mode * KK + k) * 3];
            u[k] = mc[0] * avg + mc[1] * mxv + mc[2];
            um = fmaxf(um, u[k]);
        }
        float es = 0.f;
#pragma unroll
        for (int k = 0; k < 4; k++) { u[k] = expf(u[k] - um); es += u[k]; }
        float inv = 1.f / es;
        float* U = (mode == 0) ? g_U1 : ((mode == 1) ? g_U2 : g_U3);
#pragma unroll
        for (int k = 0; k < 4; k++) U[(size_t)(b * ((mode == 0) ? CC : 64) + n) * 4 + k] = u[k] * inv;
    }
}

// ---------------- K3: spatial, ga/gm, V1 (warp-parallel) --------------------
__global__ __launch_bounds__(256) void small_kernel(const float* __restrict__ Wr,
                                                    const float* __restrict__ lam,
                                                    const float* __restrict__ ws_p,
                                                    const float* __restrict__ bs_p) {
    const int bid = blockIdx.x, tid = threadIdx.x;
    const int wid = tid >> 5, lane = tid & 31;
    if (bid < 128) {
        int g = bid * 256 + tid;
        int b = g >> 12, p = g & 4095;
        int h = p >> 6, w = p & 63;
        float4 u3 = *(const float4*)&g_U3[(b * 64 + h) * 4];
        float4 u2 = *(const float4*)&g_U2[(b * 64 + w) * 4];
        float d = u3.x * u2.x + u3.y * u2.y + u3.z * u2.z + u3.w * u2.w;
        float v = ws_p[0] * d + bs_p[0];
        g_spatial[g] = 1.f / (1.f + expf(-v));
    } else if (bid < 384) {
        int g = (bid - 128) * 8 + wid;          // b*256+c
        int b = g >> 8;
        float4 u1 = *(const float4*)&g_U1[(size_t)g * 4];
        float s = 0.f, m = -3.4e38f;
#pragma unroll
        for (int it = 0; it < 4; it++) {
            int n = it * 32 + lane;
            const float* uc = (n < 64) ? &g_U2[(b * 64 + n) * 4] : &g_U3[(b * 64 + n - 64) * 4];
            float4 u = *(const float4*)uc;
            float d = u1.x * u.x + u1.y * u.y + u1.z * u.z + u1.w * u.w;
            s += d; m = fmaxf(m, d);
        }
#pragma unroll
        for (int o = 16; o; o >>= 1) {
            s += __shfl_xor_sync(0xFFFFFFFFu, s, o);
            m = fmaxf(m, __shfl_xor_sync(0xFFFFFFFFu, m, o));
        }
        if (lane == 0) { g_ga[g] = s * (1.f / 128.f); g_gm[g] = m; }
    } else {
        int g = (bid - 384) * 8 + wid;          // b*256+o
        int b = g >> 8, o = g & 255;
        float s0 = 0.f, s1 = 0.f, s2 = 0.f, s3 = 0.f;
#pragma unroll
        for (int it = 0; it < 8; it++) {
            int i = it * 32 + lane;
            float w = Wr[(size_t)o * CC + i];
            float4 u = *(const float4*)&g_U1[(size_t)(b * CC + i) * 4];
            s0 = fmaf(w, u.x, s0); s1 = fmaf(w, u.y, s1);
            s2 = fmaf(w, u.z, s2); s3 = fmaf(w, u.w, s3);
        }
#pragma unroll
        for (int o2 = 16; o2; o2 >>= 1) {
            s0 += __shfl_xor_sync(0xFFFFFFFFu, s0, o2);
            s1 += __shfl_xor_sync(0xFFFFFFFFu, s1, o2);
            s2 += __shfl_xor_sync(0xFFFFFFFFu, s2, o2);
            s3 += __shfl_xor_sync(0xFFFFFFFFu, s3, o2);
        }
        if (lane == 0) {
            float* v = &g_V1[(size_t)g * 4];
            v[0] = lam[0] * s0; v[1] = lam[1] * s1;
            v[2] = lam[2] * s2; v[3] = lam[3] * s3;
        }
    }
}

// ---------------- K4: spectral (warp-parallel) ------------------------------
__global__ __launch_bounds__(256) void spectral_kernel(const float* __restrict__ Wsa,
                                                       const float* __restrict__ bsa,
                                                       const float* __restrict__ Wsm,
                                                       const float* __restrict__ bsm) {
    int g = blockIdx.x * 8 + (threadIdx.x >> 5);   // b*256+o
    int lane = threadIdx.x & 31;
    int b = g >> 8, o = g & 255;
    float s = 0.f;
#pragma unroll
    for (int it = 0; it < 8; it++) {
        int i = it * 32 + lane;
        s += Wsa[(size_t)o * CC + i] * g_ga[b * CC + i]
           + Wsm[(size_t)o * CC + i] * g_gm[b * CC + i];
    }
#pragma unroll
    for (int o2 = 16; o2; o2 >>= 1) s += __shfl_xor_sync(0xFFFFFFFFu, s, o2);
    if (lane == 0) {
        s += bsa[o] + bsm[o];
        float t = 1.f / (1.f + expf(-s));
        g_spec[g] = 1.f / (1.f + expf(-t));
    }
}

// ---------------- K5: fused epilogue (both outputs) -------------------------
// NOTE einsum "bcr,bhr,bwr": U2 is indexed by h, U3 by w.
__global__ __launch_bounds__(256) void epilogue_kernel(const float* __restrict__ frm,
                                                       const float* __restrict__ other,
                                                       const float* __restrict__ br,
                                                       const float* __restrict__ alpha_p,
                                                       float* __restrict__ out) {
    int e = blockIdx.x * 256 + threadIdx.x;
    int i4 = e * 4;
    int b = i4 >> 20;
    int c = (i4 >> 12) & 255;
    int h = (i4 >> 6) & 63;
    int w0 = i4 & 63;

    float alpha = alpha_p[0];
    float spec = g_spec[b * CC + c];
    const float* sp = &g_spatial[(b * HH + h) * WW + w0];
    float4 f4 = *(const float4*)&frm[i4];
    float4 o4 = *(const float4*)&other[i4];
    float4 m4 = *(const float4*)&g_Fm[i4];

    float4 v1 = *(const float4*)&g_V1[(size_t)(b * CC + c) * 4];
    float4 u2h = *(const float4*)&g_U2[(b * 64 + h) * 4];
    float vr0 = v1.x * u2h.x, vr1 = v1.y * u2h.y;
    float vr2 = v1.z * u2h.z, vr3 = v1.w * u2h.w;
    float brc = br[c];

    float fu[4], cr[4];
    float fr[4] = { f4.x, f4.y, f4.z, f4.w };
    float ot[4] = { o4.x, o4.y, o4.z, o4.w };
    float fm[4] = { m4.x, m4.y, m4.z, m4.w };
#pragma unroll
    for (int j = 0; j < 4; j++) {
        float wt = spec * sp[j];
        fu[j] = alpha * wt * fr[j] + (1.f - alpha) * (1.f - wt) * ot[j];
        float4 u3w = *(const float4*)&g_U3[(b * 64 + w0 + j) * 4];
        float cp = brc + vr0 * u3w.x + vr1 * u3w.y + vr2 * u3w.z + vr3 * u3w.w;
        cr[j] = cp * wt + fm[j];
    }
    *(float4*)&out[i4] = make_float4(fu[0], fu[1], fu[2], fu[3]);
    *(float4*)&out[NOUT + i4] = make_float4(cr[0], cr[1], cr[2], cr[3]);
}

// ---------------- launch -----------------------------------------------------
extern "C" void kernel_launch(void* const* d_in, const int* in_sizes, int n_in,
                              void* d_out, int out_size) {
    const float* frm   = (const float*)d_in[0];
    const float* other = (const float*)d_in[1];
    const float* W3    = (const float*)d_in[2];
    const float* b3    = (const float*)d_in[3];
    const float* Wa1   = (const float*)d_in[4];
    const float* ba1   = (const float*)d_in[5];
    const float* Wa2   = (const float*)d_in[6];
    const float* ba2   = (const float*)d_in[7];
    const float* Wa3   = (const float*)d_in[8];
    const float* ba3   = (const float*)d_in[9];
    const float* Wu    = (const float*)d_in[10];
    const float* bu    = (const float*)d_in[11];
    const float* Wr    = (const float*)d_in[12];
    const float* br    = (const float*)d_in[13];
    const float* ws    = (const float*)d_in[14];
    const float* bs    = (const float*)d_in[15];
    const float* Wsa   = (const float*)d_in[16];
    const float* bsa   = (const float*)d_in[17];
    const float* Wsm   = (const float*)d_in[18];
    const float* bsm   = (const float*)d_in[19];
    const float* alpha = (const float*)d_in[20];
    const float* lam   = (const float*)d_in[21];
    float* out = (float*)d_out;

    precompute_kernel<<<1, 32>>>(Wu, bu, Wa1, ba1, Wa2, ba2, Wa3, ba3);
    prep_w_kernel<<<dim3(18, 256), 256>>>(W3);
    prep_x_kernel<<<dim3(512, 8), 256>>>(frm, other);

    cudaFuncSetAttribute(conv_mma_kernel, cudaFuncAttributeMaxDynamicSharedMemorySize, DSMEM_BYTES);
    conv_mma_kernel<<<dim3(256, 2), 256, DSMEM_BYTES>>>(b3);

    modes_kernel<<<3072, 256>>>();
    small_kernel<<<640, 256>>>(Wr, lam, ws, bs);
    spectral_kernel<<<256, 256>>>(Wsa, bsa, Wsm, bsm);
    epilogue_kernel<<<NOUT / 4 / 256, 256>>>(frm, other, br, alpha, out);
}

// round 4
// speedup vs baseline: 5.2875x; 1.0345x over previous
#include <cuda_runtime.h>
#include <cuda_bf16.h>
#include <math.h>
#include <stdint.h>

// Problem constants
#define BN 8
#define CC 256
#define CI 512        // 2C
#define HH 64
#define WW 64
#define KK 4
#define HW (HH*WW)          // 4096
#define CHW (CC*HW)         // 1048576
#define NOUT (BN*CHW)       // 8388608 per tensor
#define KTOT 4608           // CI*9

// ---------------- scratch (device globals; no allocation allowed) ----------
__device__ float g_Fm[NOUT];                        // conv+leaky output (fp32 NCHW)
__device__ __nv_bfloat16 g_Xhi[BN*HH*WW*CI];        // NHWC bf16 hi
__device__ __nv_bfloat16 g_Xlo[BN*HH*WW*CI];        // NHWC bf16 lo
__device__ __nv_bfloat16 g_Whi[CC*KTOT];            // [co][tap*512+ci] hi
__device__ __nv_bfloat16 g_Wlo[CC*KTOT];            // lo
__device__ float g_U1[BN*CC*KK];
__device__ float g_U2[BN*WW*KK];
__device__ float g_U3[BN*HH*KK];
__device__ float g_Mc[3*KK*3];
__device__ float g_spatial[BN*HW];
__device__ float g_spec[BN*CC];
__device__ float g_ga[BN*CC];
__device__ float g_gm[BN*CC];
__device__ float g_V1[BN*CC*KK];
// mode pooling partials: [b][n][c] layout (n = h or w)
__device__ float g_prS[BN*64*256];   // row (per-h) sums   -> U3
__device__ float g_prM[BN*64*256];   // row maxes
__device__ float g_pcS[BN*64*256];   // col (per-w) sums   -> U2
__device__ float g_pcM[BN*64*256];   // col maxes

// ================= PTX helpers ==============================================
__device__ __forceinline__ uint32_t smem_u32(const void* p) {
    uint32_t a;
    asm("{ .reg .u64 t; cvta.to.shared.u64 t, %1; cvt.u32.u64 %0, t; }" : "=r"(a) : "l"(p));
    return a;
}
__device__ __forceinline__ void cp_async16(uint32_t dst, const void* src, uint32_t srcSize) {
    asm volatile("cp.async.ca.shared.global [%0], [%1], 16, %2;"
                 :: "r"(dst), "l"(src), "r"(srcSize) : "memory");
}
#define CP_COMMIT() asm volatile("cp.async.commit_group;" ::: "memory")
#define CP_WAIT(n)  asm volatile("cp.async.wait_group %0;" :: "n"(n) : "memory")

__device__ __forceinline__ void ldsm4(uint32_t addr, uint32_t r[4]) {
    asm volatile("ldmatrix.sync.aligned.m8n8.x4.shared.b16 {%0,%1,%2,%3}, [%4];"
                 : "=r"(r[0]), "=r"(r[1]), "=r"(r[2]), "=r"(r[3]) : "r"(addr));
}
__device__ __forceinline__ void mma16816(float c[4], const uint32_t a[4], const uint32_t b[2]) {
    asm volatile("mma.sync.aligned.m16n8k16.row.col.f32.bf16.bf16.f32 "
                 "{%0,%1,%2,%3}, {%4,%5,%6,%7}, {%8,%9}, {%0,%1,%2,%3};"
                 : "+f"(c[0]), "+f"(c[1]), "+f"(c[2]), "+f"(c[3])
                 : "r"(a[0]), "r"(a[1]), "r"(a[2]), "r"(a[3]), "r"(b[0]), "r"(b[1]));
}
#define SWZ(x) ((x) ^ (((x) >> 3) & 0x70))

// ---------------- K0: fold adapters into 2->K affine -----------------------
__global__ void precompute_kernel(const float* __restrict__ Wu, const float* __restrict__ bu,
                                  const float* __restrict__ Wa1, const float* __restrict__ ba1,
                                  const float* __restrict__ Wa2, const float* __restrict__ ba2,
                                  const float* __restrict__ Wa3, const float* __restrict__ ba3) {
    int t = threadIdx.x;
    if (t >= 12) return;
    int m = t >> 2, k = t & 3;
    const float* Wa = (m == 0) ? Wa1 : ((m == 1) ? Wa2 : Wa3);
    const float* ba = (m == 0) ? ba1 : ((m == 1) ? ba2 : ba3);
    float m0 = 0.f, m1 = 0.f, cc = 0.f;
    for (int o = 0; o < CC; o++) {
        float wu = Wu[k * CC + o];
        m0 += wu * Wa[o * 2 + 0];
        m1 += wu * Wa[o * 2 + 1];
        cc += wu * ba[o];
    }
    g_Mc[(m * KK + k) * 3 + 0] = m0;
    g_Mc[(m * KK + k) * 3 + 1] = m1;
    g_Mc[(m * KK + k) * 3 + 2] = cc + bu[k];
}

// ---------------- prep: weights -> [co][tap*512+ci] bf16 hi/lo --------------
__global__ __launch_bounds__(256) void prep_w_kernel(const float* __restrict__ W3) {
    int co = blockIdx.y;
    int r = blockIdx.x * 256 + threadIdx.x;   // 0..4607
    int tap = r >> 9, ci = r & 511;
    float v = W3[((size_t)co * CI + ci) * 9 + tap];
    __nv_bfloat16 h = __float2bfloat16_rn(v);
    __nv_bfloat16 l = __float2bfloat16_rn(v - __bfloat162float(h));
    g_Whi[(size_t)co * KTOT + r] = h;
    g_Wlo[(size_t)co * KTOT + r] = l;
}

// ---------------- prep: inputs NCHW fp32 -> NHWC bf16 hi/lo -----------------
__global__ __launch_bounds__(256) void prep_x_kernel(const float* __restrict__ frm,
                                                     const float* __restrict__ other) {
    __shared__ float S[64][65];
    int by = blockIdx.x;           // b*64 + y
    int b = by >> 6, y = by & 63;
    int cc = blockIdx.y;           // ci chunk of 64
    int tid = threadIdx.x;
#pragma unroll
    for (int i = 0; i < 16; i++) {
        int idx = i * 256 + tid;
        int ciL = idx >> 6, x = idx & 63;
        int ciX = cc * 64 + ciL;
        const float* src = (ciX < CC) ? frm : other;
        int cs = ciX & 255;
        S[ciL][x] = src[((size_t)(b * CC + cs) * HH + y) * WW + x];
    }
    __syncthreads();
#pragma unroll
    for (int i = 0; i < 16; i++) {
        int idx = i * 256 + tid;
        int x = idx >> 6, ciL = idx & 63;
        float v = S[ciL][x];
        __nv_bfloat16 h = __float2bfloat16_rn(v);
        __nv_bfloat16 l = __float2bfloat16_rn(v - __bfloat162float(h));
        size_t d = ((size_t)(b * 64 + y) * 64 + x) * CI + cc * 64 + ciL;
        g_Xhi[d] = h;
        g_Xlo[d] = l;
    }
}

// ---------------- conv via mma.sync bf16x3 implicit GEMM --------------------
// CTA: M=128 pixels (2 rows), N=128 co. 8 warps = 4M x 2N, warp tile 32x64.
// K = 72 chunks of 64 (9 taps x 8 ci-chunks). 3 SMEM stages, 1 sync/iter.
#define STAGE_BYTES 65536
#define DSMEM_BYTES (3*STAGE_BYTES + 1024)

__device__ __forceinline__ void stage_load(uint32_t smStage, int b, int y0, int n0,
                                           int c, int tid) {
    const int tap = c >> 3, cic = c & 7;
    const int ky = tap / 3 - 1, kx = tap % 3 - 1;
#pragma unroll
    for (int i = 0; i < 8; i++) {
        int idx = i * 256 + tid;
        int plane = idx >> 10, rem = idx & 1023;
        int r = rem >> 3, q = rem & 7;
        int ys = y0 + (r >> 6) + ky, xs = (r & 63) + kx;
        bool ok = ((unsigned)ys < 64u) && ((unsigned)xs < 64u);
        const __nv_bfloat16* base = plane ? g_Xlo : g_Xhi;
        const void* src = ok
            ? (const void*)(base + (((size_t)(b * 64 + ys) * 64 + xs) * CI + cic * 64 + q * 8))
            : (const void*)base;
        uint32_t full = (uint32_t)(r * 128 + q * 16);
        cp_async16(smStage + plane * 16384 + SWZ(full), src, ok ? 16u : 0u);
    }
#pragma unroll
    for (int i = 0; i < 8; i++) {
        int idx = i * 256 + tid;
        int plane = idx >> 10, rem = idx & 1023;
        int r = rem >> 3, q = rem & 7;
        const __nv_bfloat16* base = plane ? g_Wlo : g_Whi;
        const void* src = base + ((size_t)(n0 * 128 + r) * KTOT + c * 64 + q * 8);
        uint32_t full = (uint32_t)(r * 128 + q * 16);
        cp_async16(smStage + 32768 + plane * 16384 + SWZ(full), src, 16u);
    }
}

__global__ __launch_bounds__(256, 1)
void conv_mma_kernel(const float* __restrict__ b3) {
    extern __shared__ __align__(128) char dynsm_raw[];
    const uint32_t smBase = (smem_u32(dynsm_raw) + 1023) & ~1023u;

    const int tid = threadIdx.x;
    const int lane = tid & 31;
    const int w = tid >> 5;
    const int wm = w & 3, wn = w >> 2;
    const int mIdx = blockIdx.x;
    const int b = mIdx >> 5;
    const int y0 = (mIdx & 31) * 2;
    const int n0 = blockIdx.y;

    float acc[2][8][4];
#pragma unroll
    for (int mf = 0; mf < 2; mf++)
#pragma unroll
        for (int nf = 0; nf < 8; nf++)
#pragma unroll
            for (int j = 0; j < 4; j++) acc[mf][nf][j] = 0.f;

    // fragment address components (bytes within region)
    const uint32_t aRowOff = (uint32_t)((wm * 32 + (lane & 15)) * 128);
    const uint32_t aColB   = (uint32_t)((lane >> 4) * 16);
    const uint32_t bRowOff = (uint32_t)((wn * 64 + (lane & 7) + ((lane >> 4) << 3)) * 128);
    const uint32_t bColB   = (uint32_t)(((lane >> 3) & 1) * 16);

    stage_load(smBase, b, y0, n0, 0, tid);
    CP_COMMIT();
    stage_load(smBase + STAGE_BYTES, b, y0, n0, 1, tid);
    CP_COMMIT();

    int sCur = 0, sNxt = 2;
    for (int c = 0; c < 72; c++) {
        if (c < 71) { CP_WAIT(1); } else { CP_WAIT(0); }
        __syncthreads();   // all warps: stage sCur ready AND done computing c-1

        // issue prefetch for c+2 into the stage freed by c-1 (safe post-barrier)
        if (c + 2 < 72) {
            stage_load(smBase + (uint32_t)sNxt * STAGE_BYTES, b, y0, n0, c + 2, tid);
            CP_COMMIT();
        }

        const uint32_t st = smBase + (uint32_t)sCur * STAGE_BYTES;
#pragma unroll
        for (int k16 = 0; k16 < 4; k16++) {
            const uint32_t kb = (uint32_t)(k16 * 32);
            uint32_t ah[2][4], al[2][4], bh[8][2], bl[8][2];
#pragma unroll
            for (int mf = 0; mf < 2; mf++) {
                uint32_t aAddr = st + SWZ(aRowOff + (uint32_t)(mf * 2048) + aColB + kb);
                ldsm4(aAddr, ah[mf]);
                ldsm4(aAddr + 16384, al[mf]);
            }
#pragma unroll
            for (int jp = 0; jp < 4; jp++) {
                uint32_t bAddr = st + 32768 + SWZ(bRowOff + (uint32_t)(jp * 2048) + bColB + kb);
                uint32_t rh[4], rl[4];
                ldsm4(bAddr, rh);
                ldsm4(bAddr + 16384, rl);
                bh[2 * jp][0] = rh[0]; bh[2 * jp][1] = rh[1];
                bh[2 * jp + 1][0] = rh[2]; bh[2 * jp + 1][1] = rh[3];
                bl[2 * jp][0] = rl[0]; bl[2 * jp][1] = rl[1];
                bl[2 * jp + 1][0] = rl[2]; bl[2 * jp + 1][1] = rl[3];
            }
#pragma unroll
            for (int mf = 0; mf < 2; mf++)
#pragma unroll
                for (int nf = 0; nf < 8; nf++) mma16816(acc[mf][nf], ah[mf], bh[nf]);
#pragma unroll
            for (int mf = 0; mf < 2; mf++)
#pragma unroll
                for (int nf = 0; nf < 8; nf++) mma16816(acc[mf][nf], ah[mf], bl[nf]);
#pragma unroll
            for (int mf = 0; mf < 2; mf++)
#pragma unroll
                for (int nf = 0; nf < 8; nf++) mma16816(acc[mf][nf], al[mf], bh[nf]);
        }
        sCur = (sCur == 2) ? 0 : sCur + 1;
        sNxt = (sNxt == 2) ? 0 : sNxt + 1;
    }

    // epilogue: bias + leaky relu -> g_Fm (NCHW)
    const int rr = wm * 32 + (lane >> 2);
    const int cc0 = n0 * 128 + wn * 64 + (lane & 3) * 2;
    const int pixBase = y0 * 64;
#pragma unroll
    for (int mf = 0; mf < 2; mf++) {
        int r0 = rr + mf * 16;
#pragma unroll
        for (int nf = 0; nf < 8; nf++) {
            int co = cc0 + nf * 8;
            float bi0 = __ldg(&b3[co]), bi1 = __ldg(&b3[co + 1]);
            float v0 = acc[mf][nf][0] + bi0;
            float v1 = acc[mf][nf][1] + bi1;
            float v2 = acc[mf][nf][2] + bi0;
            float v3 = acc[mf][nf][3] + bi1;
            v0 = (v0 > 0.f) ? v0 : 0.01f * v0;
            v1 = (v1 > 0.f) ? v1 : 0.01f * v1;
            v2 = (v2 > 0.f) ? v2 : 0.01f * v2;
            v3 = (v3 > 0.f) ? v3 : 0.01f * v3;
            size_t base0 = ((size_t)(b * CC + co) << 12) + pixBase;
            size_t base1 = ((size_t)(b * CC + co + 1) << 12) + pixBase;
            g_Fm[base0 + r0] = v0;
            g_Fm[base1 + r0] = v1;
            g_Fm[base0 + r0 + 8] = v2;
            g_Fm[base1 + r0 + 8] = v3;
        }
    }
}

// ---------------- modes pass1: one coalesced sweep per (b,c) plane ----------
// Produces: U1 directly (block-local pooling), per-h and per-w partials.
__global__ __launch_bounds__(256) void modes_pass1_kernel() {
    const int bc = blockIdx.x;            // b*256 + c
    const int b = bc >> 8, c = bc & 255;
    const float* p = g_Fm + ((size_t)bc << 12);
    const int tid = threadIdx.x, lane = tid & 31, warp = tid >> 5;

    __shared__ float wRS[16][8], wRM[16][8];   // [i][warp] row partials
    __shared__ float cPS[4][64], cPM[4][64];   // [tid>>6][w] col partials
    __shared__ float rS[256], rM[256];

    float tS = 0.f, tM = -3.4e38f, cS = 0.f, cM = -3.4e38f;
#pragma unroll
    for (int i = 0; i < 16; i++) {
        float v = p[i * 256 + tid];
        tS += v; tM = fmaxf(tM, v);
        cS += v; cM = fmaxf(cM, v);
        float rs = v, rm = v;
#pragma unroll
        for (int o = 16; o; o >>= 1) {
            rs += __shfl_xor_sync(0xFFFFFFFFu, rs, o);
            rm = fmaxf(rm, __shfl_xor_sync(0xFFFFFFFFu, rm, o));
        }
        if (lane == 0) { wRS[i][warp] = rs; wRM[i][warp] = rm; }
    }
    cPS[tid >> 6][tid & 63] = cS;
    cPM[tid >> 6][tid & 63] = cM;
    rS[tid] = tS; rM[tid] = tM;
    __syncthreads();
    for (int st = 128; st; st >>= 1) {
        if (tid < st) { rS[tid] += rS[tid + st]; rM[tid] = fmaxf(rM[tid], rM[tid + st]); }
        __syncthreads();
    }
    if (tid < 64) {                       // h = tid ; row pools -> U3 partials
        int i = tid >> 2, wp2 = tid & 3;
        g_prS[(b * 64 + tid) * 256 + c] = wRS[i][2 * wp2] + wRS[i][2 * wp2 + 1];
        g_prM[(b * 64 + tid) * 256 + c] = fmaxf(wRM[i][2 * wp2], wRM[i][2 * wp2 + 1]);
    } else if (tid < 128) {               // w = tid-64 ; col pools -> U2 partials
        int wq = tid - 64;
        g_pcS[(b * 64 + wq) * 256 + c] = cPS[0][wq] + cPS[1][wq] + cPS[2][wq] + cPS[3][wq];
        g_pcM[(b * 64 + wq) * 256 + c] =
            fmaxf(fmaxf(cPM[0][wq], cPM[1][wq]), fmaxf(cPM[2][wq], cPM[3][wq]));
    } else if (tid == 128) {              // U1[b,c,:]
        float avg = rS[0] * (1.f / 4096.f), mx = rM[0];
        float u[4], um = -3.4e38f;
#pragma unroll
        for (int k = 0; k < 4; k++) {
            const float* mc = &g_Mc[(0 * KK + k) * 3];
            u[k] = mc[0] * avg + mc[1] * mx + mc[2];
            um = fmaxf(um, u[k]);
        }
        float es = 0.f;
#pragma unroll
        for (int k = 0; k < 4; k++) { u[k] = expf(u[k] - um); es += u[k]; }
        float inv = 1.f / es;
#pragma unroll
        for (int k = 0; k < 4; k++) g_U1[bc * 4 + k] = u[k] * inv;
    }
}

// ---------------- modes finalize: reduce 256 c-partials, softmax ------------
__global__ __launch_bounds__(256) void modes_final_kernel() {
    int gw = blockIdx.x * 8 + (threadIdx.x >> 5);   // 0..1023
    int lane = threadIdx.x & 31;
    int isU2 = (gw < 512);
    int e = isU2 ? gw : gw - 512;                    // b*64 + n
    const float* pS = isU2 ? g_pcS : g_prS;
    const float* pM = isU2 ? g_pcM : g_prM;
    float s = 0.f, m = -3.4e38f;
#pragma unroll
    for (int it = 0; it < 8; it++) {
        int i = it * 32 + lane;
        s += pS[e * 256 + i];
        m = fmaxf(m, pM[e * 256 + i]);
    }
#pragma unroll
    for (int o = 16; o; o >>= 1) {
        s += __shfl_xor_sync(0xFFFFFFFFu, s, o);
        m = fmaxf(m, __shfl_xor_sync(0xFFFFFFFFu, m, o));
    }
    if (lane == 0) {
        float avg = s * (1.f / 16384.f);
        int mode = isU2 ? 1 : 2;
        float u[4], um = -3.4e38f;
#pragma unroll
        for (int k = 0; k < 4; k++) {
            const float* mc = &g_Mc[(mode * KK + k) * 3];
            u[k] = mc[0] * avg + mc[1] * m + mc[2];
            um = fmaxf(um, u[k]);
        }
        float es = 0.f;
#pragma unroll
        for (int k = 0; k < 4; k++) { u[k] = expf(u[k] - um); es += u[k]; }
        float inv = 1.f / es;
        float* U = isU2 ? g_U2 : g_U3;
#pragma unroll
        for (int k = 0; k < 4; k++) U[e * 4 + k] = u[k] * inv;
    }
}

// ---------------- K3: spatial, ga/gm, V1 (warp-parallel) --------------------
__global__ __launch_bounds__(256) void small_kernel(const float* __restrict__ Wr,
                                                    const float* __restrict__ lam,
                                                    const float* __restrict__ ws_p,
                                                    const float* __restrict__ bs_p) {
    const int bid = blockIdx.x, tid = threadIdx.x;
    const int wid = tid >> 5, lane = tid & 31;
    if (bid < 128) {
        int g = bid * 256 + tid;
        int b = g >> 12, p = g & 4095;
        int h = p >> 6, w = p & 63;
        float4 u3 = *(const float4*)&g_U3[(b * 64 + h) * 4];
        float4 u2 = *(const float4*)&g_U2[(b * 64 + w) * 4];
        float d = u3.x * u2.x + u3.y * u2.y + u3.z * u2.z + u3.w * u2.w;
        float v = ws_p[0] * d + bs_p[0];
        g_spatial[g] = 1.f / (1.f + expf(-v));
    } else if (bid < 384) {
        int g = (bid - 128) * 8 + wid;          // b*256+c
        int b = g >> 8;
        float4 u1 = *(const float4*)&g_U1[(size_t)g * 4];
        float s = 0.f, m = -3.4e38f;
#pragma unroll
        for (int it = 0; it < 4; it++) {
            int n = it * 32 + lane;
            const float* uc = (n < 64) ? &g_U2[(b * 64 + n) * 4] : &g_U3[(b * 64 + n - 64) * 4];
            float4 u = *(const float4*)uc;
            float d = u1.x * u.x + u1.y * u.y + u1.z * u.z + u1.w * u.w;
            s += d; m = fmaxf(m, d);
        }
#pragma unroll
        for (int o = 16; o; o >>= 1) {
            s += __shfl_xor_sync(0xFFFFFFFFu, s, o);
            m = fmaxf(m, __shfl_xor_sync(0xFFFFFFFFu, m, o));
        }
        if (lane == 0) { g_ga[g] = s * (1.f / 128.f); g_gm[g] = m; }
    } else {
        int g = (bid - 384) * 8 + wid;          // b*256+o
        int b = g >> 8, o = g & 255;
        float s0 = 0.f, s1 = 0.f, s2 = 0.f, s3 = 0.f;
#pragma unroll
        for (int it = 0; it < 8; it++) {
            int i = it * 32 + lane;
            float w = Wr[(size_t)o * CC + i];
            float4 u = *(const float4*)&g_U1[(size_t)(b * CC + i) * 4];
            s0 = fmaf(w, u.x, s0); s1 = fmaf(w, u.y, s1);
            s2 = fmaf(w, u.z, s2); s3 = fmaf(w, u.w, s3);
        }
#pragma unroll
        for (int o2 = 16; o2; o2 >>= 1) {
            s0 += __shfl_xor_sync(0xFFFFFFFFu, s0, o2);
            s1 += __shfl_xor_sync(0xFFFFFFFFu, s1, o2);
            s2 += __shfl_xor_sync(0xFFFFFFFFu, s2, o2);
            s3 += __shfl_xor_sync(0xFFFFFFFFu, s3, o2);
        }
        if (lane == 0) {
            float* v = &g_V1[(size_t)g * 4];
            v[0] = lam[0] * s0; v[1] = lam[1] * s1;
            v[2] = lam[2] * s2; v[3] = lam[3] * s3;
        }
    }
}

// ---------------- K4: spectral (warp-parallel) ------------------------------
__global__ __launch_bounds__(256) void spectral_kernel(const float* __restrict__ Wsa,
                                                       const float* __restrict__ bsa,
                                                       const float* __restrict__ Wsm,
                                                       const float* __restrict__ bsm) {
    int g = blockIdx.x * 8 + (threadIdx.x >> 5);   // b*256+o
    int lane = threadIdx.x & 31;
    int b = g >> 8, o = g & 255;
    float s = 0.f;
#pragma unroll
    for (int it = 0; it < 8; it++) {
        int i = it * 32 + lane;
        s += Wsa[(size_t)o * CC + i] * g_ga[b * CC + i]
           + Wsm[(size_t)o * CC + i] * g_gm[b * CC + i];
    }
#pragma unroll
    for (int o2 = 16; o2; o2 >>= 1) s += __shfl_xor_sync(0xFFFFFFFFu, s, o2);
    if (lane == 0) {
        s += bsa[o] + bsm[o];
        float t = 1.f / (1.f + expf(-s));
        g_spec[g] = 1.f / (1.f + expf(-t));
    }
}

// ---------------- K5: fused epilogue (both outputs) -------------------------
// NOTE einsum "bcr,bhr,bwr": U2 is indexed by h, U3 by w.
__global__ __launch_bounds__(256) void epilogue_kernel(const float* __restrict__ frm,
                                                       const float* __restrict__ other,
                                                       const float* __restrict__ br,
                                                       const float* __restrict__ alpha_p,
                                                       float* __restrict__ out) {
    int e = blockIdx.x * 256 + threadIdx.x;
    int i4 = e * 4;
    int b = i4 >> 20;
    int c = (i4 >> 12) & 255;
    int h = (i4 >> 6) & 63;
    int w0 = i4 & 63;

    float alpha = alpha_p[0];
    float spec = g_spec[b * CC + c];
    const float* sp = &g_spatial[(b * HH + h) * WW + w0];
    float4 f4 = *(const float4*)&frm[i4];
    float4 o4 = *(const float4*)&other[i4];
    float4 m4 = *(const float4*)&g_Fm[i4];

    float4 v1 = *(const float4*)&g_V1[(size_t)(b * CC + c) * 4];
    float4 u2h = *(const float4*)&g_U2[(b * 64 + h) * 4];
    float vr0 = v1.x * u2h.x, vr1 = v1.y * u2h.y;
    float vr2 = v1.z * u2h.z, vr3 = v1.w * u2h.w;
    float brc = br[c];

    float fu[4], cr[4];
    float fr[4] = { f4.x, f4.y, f4.z, f4.w };
    float ot[4] = { o4.x, o4.y, o4.z, o4.w };
    float fm[4] = { m4.x, m4.y, m4.z, m4.w };
#pragma unroll
    for (int j = 0; j < 4; j++) {
        float wt = spec * sp[j];
        fu[j] = alpha * wt * fr[j] + (1.f - alpha) * (1.f - wt) * ot[j];
        float4 u3w = *(const float4*)&g_U3[(b * 64 + w0 + j) * 4];
        float cp = brc + vr0 * u3w.x + vr1 * u3w.y + vr2 * u3w.z + vr3 * u3w.w;
        cr[j] = cp * wt + fm[j];
    }
    *(float4*)&out[i4] = make_float4(fu[0], fu[1], fu[2], fu[3]);
    *(float4*)&out[NOUT + i4] = make_float4(cr[0], cr[1], cr[2], cr[3]);
}

// ---------------- launch -----------------------------------------------------
extern "C" void kernel_launch(void* const* d_in, const int* in_sizes, int n_in,
                              void* d_out, int out_size) {
    const float* frm   = (const float*)d_in[0];
    const float* other = (const float*)d_in[1];
    const float* W3    = (const float*)d_in[2];
    const float* b3    = (const float*)d_in[3];
    const float* Wa1   = (const float*)d_in[4];
    const float* ba1   = (const float*)d_in[5];
    const float* Wa2   = (const float*)d_in[6];
    const float* ba2   = (const float*)d_in[7];
    const float* Wa3   = (const float*)d_in[8];
    const float* ba3   = (const float*)d_in[9];
    const float* Wu    = (const float*)d_in[10];
    const float* bu    = (const float*)d_in[11];
    const float* Wr    = (const float*)d_in[12];
    const float* br    = (const float*)d_in[13];
    const float* ws    = (const float*)d_in[14];
    const float* bs    = (const float*)d_in[15];
    const float* Wsa   = (const float*)d_in[16];
    const float* bsa   = (const float*)d_in[17];
    const float* Wsm   = (const float*)d_in[18];
    const float* bsm   = (const float*)d_in[19];
    const float* alpha = (const float*)d_in[20];
    const float* lam   = (const float*)d_in[21];
    float* out = (float*)d_out;

    precompute_kernel<<<1, 32>>>(Wu, bu, Wa1, ba1, Wa2, ba2, Wa3, ba3);
    prep_w_kernel<<<dim3(18, 256), 256>>>(W3);
    prep_x_kernel<<<dim3(512, 8), 256>>>(frm, other);

    cudaFuncSetAttribute(conv_mma_kernel, cudaFuncAttributeMaxDynamicSharedMemorySize, DSMEM_BYTES);
    conv_mma_kernel<<<dim3(256, 2), 256, DSMEM_BYTES>>>(b3);

    modes_pass1_kernel<<<2048, 256>>>();
    modes_final_kernel<<<128, 256>>>();
    small_kernel<<<640, 256>>>(Wr, lam, ws, bs);
    spectral_kernel<<<256, 256>>>(Wsa, bsa, Wsm, bsm);
    epilogue_kernel<<<NOUT / 4 / 256, 256>>>(frm, other, br, alpha, out);
}